// round 15
// baseline (speedup 1.0000x reference)
#include <cuda_runtime.h>

#define NV 256   // vertices
#define KD 16    // degree
#define HD 32    // hidden

// ---------------- globals ----------------
__device__ float g_F1[NV * 256 * HD];       // layer-1 output, SWIZZLED per-vertex blocks
__device__ unsigned g_flag[NV];             // per-vertex publish flag (epoch-stamped)
__device__ unsigned g_epoch;
__device__ unsigned g_done;
__device__ float g_acc;

typedef unsigned long long ull;

__device__ __forceinline__ ull pack2(float x) {
    ull r; asm("mov.b64 %0, {%1, %1};" : "=l"(r) : "f"(x)); return r;
}
__device__ __forceinline__ ull pack2f(float lo, float hi) {
    ull r; asm("mov.b64 %0, {%1, %2};" : "=l"(r) : "f"(lo), "f"(hi)); return r;
}
__device__ __forceinline__ void unpack2(ull v, float& lo, float& hi) {
    asm("mov.b64 {%0, %1}, %2;" : "=f"(lo), "=f"(hi) : "l"(v));
}
__device__ __forceinline__ void dfma(ull& acc, ull a, ull b) {
    asm("fma.rn.f32x2 %0, %1, %2, %0;" : "+l"(acc) : "l"(a), "l"(b));
}
__device__ __forceinline__ ull addx2(ull a, ull b) {
    ull r; asm("add.rn.f32x2 %0, %1, %2;" : "=l"(r) : "l"(a), "l"(b)); return r;
}
__device__ __forceinline__ void gemm_row(ull* y, ull a, const float* wrow) {
    const longlong2* w = (const longlong2*)wrow;
#pragma unroll
    for (int k8 = 0; k8 < 8; k8++) {
        longlong2 v = w[k8];
        dfma(y[2 * k8 + 0], a, (ull)v.x);
        dfma(y[2 * k8 + 1], a, (ull)v.y);
    }
}

// ---------------- mbarrier + bulk-copy helpers ----------------
#define MBAR_INIT(addr) \
    asm volatile("mbarrier.init.shared.b64 [%0], 1;" :: "r"(addr) : "memory")
#define MBAR_EXPECT(addr, bytes) \
    asm volatile("mbarrier.arrive.expect_tx.shared.b64 _, [%0], %1;" :: "r"(addr), "r"(bytes) : "memory")
#define MBAR_WAIT(addr, par) do { \
    asm volatile("{\n\t.reg .pred P;\n\tWL_%=:\n\tmbarrier.try_wait.parity.acquire.cta.shared::cta.b64 P, [%0], %1, 0x989680;\n\t@!P bra WL_%=;\n\t}" \
        :: "r"(addr), "r"(par) : "memory"); \
} while (0)
__device__ __forceinline__ void bulk_tile(unsigned sdst, const float* gsrc, unsigned mbar) {
    asm volatile("cp.async.bulk.shared::cta.global.mbarrier::complete_tx::bytes [%0], [%1], 32768, [%2];"
        :: "r"(sdst), "l"(gsrc), "r"(mbar) : "memory");
}

// ---------------- smem layout (floats) ----------------
#define OFF_W     0          // 6144 : Wc1 (first 3072) then Wc2 [slots; 0 and 5 transposed]
#define OFF_T0    6144       // 8192 : tile0 (layer1 scratch aliases here)
#define OFF_T1    14336      // 8192 : tile1 (layer1 staging buffer)
#define OFF_GT    22528      // 1728 : sGt triple buffer [3][16][36]
#define OFF_DG    24256      // 1728 : sDiag triple buffer
#define OFF_SAB   25984      // 512
#define OFF_STB   26496      // 512
#define OFF_SAL   27008      // 32
#define OFF_YB    27040      // 1088 : ull[2][272]; OVERLAY: sU(512)+sD(32)+sRED(32) post-pickup
#define OFF_INT   28128      // nbr16,qm16,vm16,cnt16,misc4,mbar(4),M(64w) = 136 floats
#define SMEM_FLOATS (28128 + 136)
#define SMEM_BYTES  (SMEM_FLOATS * 4)

// pair-tile collaborative gb/dg gemm with TRANSPOSED weights (w rows = [h-pair][c] ull)
__device__ __forceinline__ void collab_pair(const float* gA, const float* dA,
                                            const float* gB, const float* dB,
                                            const longlong2* w0r, const longlong2* w5r,
                                            ull* outA, ull* outB) {
    ull a0 = 0, a1 = 0, b0 = 0, b1 = 0;
#pragma unroll
    for (int c4 = 0; c4 < 8; c4++) {
        float4 ga = *(const float4*)(gA + c4 * 4);
        float4 da = *(const float4*)(dA + c4 * 4);
        float4 gb = *(const float4*)(gB + c4 * 4);
        float4 db = *(const float4*)(dB + c4 * 4);
        longlong2 w00 = w0r[2 * c4], w01 = w0r[2 * c4 + 1];
        longlong2 w50 = w5r[2 * c4], w51 = w5r[2 * c4 + 1];
        dfma(a0, pack2(ga.x), (ull)w00.x);
        dfma(b0, pack2(gb.x), (ull)w00.x);
        dfma(a1, pack2(da.x), (ull)w50.x);
        dfma(b1, pack2(db.x), (ull)w50.x);
        dfma(a0, pack2(ga.y), (ull)w00.y);
        dfma(b0, pack2(gb.y), (ull)w00.y);
        dfma(a1, pack2(da.y), (ull)w50.y);
        dfma(b1, pack2(db.y), (ull)w50.y);
        dfma(a0, pack2(ga.z), (ull)w01.x);
        dfma(b0, pack2(gb.z), (ull)w01.x);
        dfma(a1, pack2(da.z), (ull)w51.x);
        dfma(b1, pack2(db.z), (ull)w51.x);
        dfma(a0, pack2(ga.w), (ull)w01.y);
        dfma(b0, pack2(gb.w), (ull)w01.y);
        dfma(a1, pack2(da.w), (ull)w51.y);
        dfma(b1, pack2(db.w), (ull)w51.y);
    }
    *outA = addx2(a0, a1);
    *outB = addx2(b0, b1);
}

__device__ __forceinline__ void phaseA(int t, const float4* bufv, float* sGt, float* sDg,
                                       const unsigned* sQM, const signed char* sM,
                                       int aA, int half, int c4A, ull& stbA, ull& stbB) {
    int par = (t % 3) * 576;
    unsigned qm = sQM[t];
    int pA = sM[t * 16 + aA];
    ull acc0 = 0ull, acc1 = 0ull;
    if (pA >= 0) {
        int rbase = pA * 16 + half * 8;
#pragma unroll
        for (int k = 0; k < 8; k++) {
            if (qm & (1u << (half * 8 + k))) {
                int r = rbase + k;
                longlong2 v = *(const longlong2*)(bufv + r * 8 + (c4A ^ (r & 7)));
                acc0 = addx2(acc0, (ull)v.x);
                acc1 = addx2(acc1, (ull)v.y);
            }
        }
    }
    float f0, f1, f2, f3;
    unpack2(acc0, f0, f1);
    unpack2(acc1, f2, f3);
    f0 += __shfl_xor_sync(0xffffffffu, f0, 8);
    f1 += __shfl_xor_sync(0xffffffffu, f1, 8);
    f2 += __shfl_xor_sync(0xffffffffu, f2, 8);
    f3 += __shfl_xor_sync(0xffffffffu, f3, 8);
    stbA = addx2(stbA, pack2f(f0, f1));
    stbB = addx2(stbB, pack2f(f2, f3));
    if (half == 0) {
        float4 o; o.x = f0; o.y = f1; o.z = f2; o.w = f3;
        *(float4*)(sGt + par + aA * 36 + c4A * 4) = o;
    } else {
        longlong2 dv; dv.x = 0; dv.y = 0;
        if (pA >= 0) {
            int rd = pA * 17;
            dv = *(const longlong2*)(bufv + rd * 8 + (c4A ^ (rd & 7)));
        }
        *(longlong2*)(sDg + par + aA * 36 + c4A * 4) = dv;
    }
}

__device__ __forceinline__ void stGather(int t, const float4* bufv, const signed char* sM,
                                         int i, int j, ull* st2) {
    int pa = sM[t * 16 + i], pb = sM[t * 16 + j];
    if ((pa | pb) >= 0) {
        int r = pa * 16 + pb;
#pragma unroll
        for (int c4 = 0; c4 < 8; c4++) {
            longlong2 v = *(const longlong2*)(bufv + r * 8 + (c4 ^ (r & 7)));
            st2[2 * c4 + 0] = addx2(st2[2 * c4 + 0], (ull)v.x);
            st2[2 * c4 + 1] = addx2(st2[2 * c4 + 1], (ull)v.y);
        }
    }
}

__global__ __launch_bounds__(256, 2) void ccn_fused(const int* __restrict__ nbrs,
                                                    const float* __restrict__ X,
                                                    const float* __restrict__ W1,
                                                    const float* __restrict__ b1,
                                                    const float* __restrict__ W2,
                                                    const float* __restrict__ b2,
                                                    const float* __restrict__ fcw,
                                                    const float* __restrict__ fcb,
                                                    float* __restrict__ out) {
    extern __shared__ float smem[];
    float* sW    = smem + OFF_W;
    float* tile0 = smem + OFF_T0;
    float* tile1 = smem + OFF_T1;
    float* sGt   = smem + OFF_GT;    // [3][16][36]
    float* sDg   = smem + OFF_DG;    // [3][16][36]
    float* sSAB  = smem + OFF_SAB;   // [16][32]
    float* sSTB  = smem + OFF_STB;   // [16][32]
    float* sSAL  = smem + OFF_SAL;
    ull*   sYB   = (ull*)(smem + OFF_YB);     // [2][272]; overlaid by sU/sD/sRED later
    float* sU    = smem + OFF_YB;             // valid after pickup barrier
    float* sD    = sU + 512;
    float* sRED  = sU + 544;
    int*      sNbr = (int*)(smem + OFF_INT);
    unsigned* sQM  = (unsigned*)(sNbr + 16);
    unsigned* sVM  = (unsigned*)(sQM + 16);
    float*    sCnt = (float*)(sVM + 16);
    unsigned* sMisc = (unsigned*)(sCnt + 16);        // 4
    ull*      sMbar = (ull*)(sMisc + 4);             // 2 mbarriers
    signed char* sM = (signed char*)(sMbar + 2);     // 256

    // layer-1 scratch aliases inside tile0
    float* sXn  = tile0;          // 256
    float* sAB1 = tile0 + 256;    // 256
    float* sTB1 = tile0 + 512;    // 256
    float* sAL1 = tile0 + 768;    // 16
    float* sU1  = tile0 + 784;    // 512
    float* sD1  = tile0 + 1296;   // 32
    float* sB1  = tile0 + 1328;   // 32
    float* sR   = tile0 + 1360;   // 512 : per-row xv-term table
    float* sZ   = tile0 + 1872;   // 512 : Z = Xn @ W2b

    int n = blockIdx.x, tid = threadIdx.x;
    int i = tid >> 4, j = tid & 15;
    int aA = i;                    // phase-A row
    int half = (tid >> 3) & 1;     // phase-A q-half
    int c4A = tid & 7;             // phase-A float4 column

    unsigned mb0 = (unsigned)__cvta_generic_to_shared(sMbar);
    unsigned mb1 = mb0 + 8;
    unsigned t0a = (unsigned)__cvta_generic_to_shared(tile0);
    unsigned t1a = (unsigned)__cvta_generic_to_shared(tile1);

    // ============ stage 0 ============
    {
        int jv = nbrs[n * 16 + i];
        int target = nbrs[n * 16 + j];
        int r = -1;
#pragma unroll
        for (int p = 0; p < 16; p++)
            if (nbrs[jv * 16 + p] == target) r = p;
        sM[tid] = (signed char)r;                 // sM[t*16+a], t=i, a=j
        sXn[tid] = X[jv * 16 + j];
    }
    if (tid < 16) sNbr[tid] = nbrs[n * 16 + tid];
    if (tid == 0) {
        sMisc[0] = g_epoch;
        MBAR_INIT(mb0);
        MBAR_INIT(mb1);
    }
    // Wc1 (C=16): slot0=16*(W0+W6..14)+W5, 1=W1, 2=16*W2, 3=W3, 4=W4, 5=W15 (row-major)
    for (int idx = tid; idx < 512; idx += 256) {
        int c = idx >> 5, h = idx & 31;
        float s = W1[(0 * 16 + c) * 32 + h];
#pragma unroll
        for (int m = 6; m < 15; m++) s += W1[(m * 16 + c) * 32 + h];
        sW[0 * 512 + c * 32 + h] = 16.0f * s + W1[(5 * 16 + c) * 32 + h];
        sW[1 * 512 + c * 32 + h] = W1[(1 * 16 + c) * 32 + h];
        sW[2 * 512 + c * 32 + h] = 16.0f * W1[(2 * 16 + c) * 32 + h];
        sW[3 * 512 + c * 32 + h] = W1[(3 * 16 + c) * 32 + h];
        sW[4 * 512 + c * 32 + h] = W1[(4 * 16 + c) * 32 + h];
        sW[5 * 512 + c * 32 + h] = W1[(15 * 16 + c) * 32 + h];
    }
    if (tid < HD) sB1[tid] = b1[tid];
    __syncthreads();
    if (tid < 16) {
        unsigned vm = 0, qm = 0;
#pragma unroll
        for (int a = 0; a < 16; a++) {
            int p = sM[tid * 16 + a];
            if (p >= 0) { vm |= 1u << a; qm |= 1u << p; }
        }
        sVM[tid] = vm;
        sQM[tid] = qm;
        sCnt[tid] = (float)__popc(vm);
    }
    __syncthreads();

    // ============ layer 1 (closed forms + row-shared tables) ============
    sAB1[tid] = sCnt[i] * sCnt[i] * sXn[tid];
    {
        float s = 0.0f;
#pragma unroll
        for (int t = 0; t < 16; t++)
            if ((sVM[t] >> i) & 1) s += sCnt[t] * sXn[t * 16 + j];
        sTB1[tid] = s;
    }
    // R[row][h] = cnt_row*(Xn_row @ Wsb)[h] + (Xn_row @ W15)[h];  Z[row][h] = (Xn_row @ W2b)[h]
#pragma unroll
    for (int rep = 0; rep < 2; rep++) {
        int idx = tid + rep * 256;
        int row = idx >> 5, h = idx & 31;
        float a1 = 0.0f, a2 = 0.0f, zz = 0.0f;
#pragma unroll
        for (int c = 0; c < 16; c++) {
            float xv = sXn[row * 16 + c];
            a1 += xv * sW[0 * 512 + c * 32 + h];
            zz += xv * sW[2 * 512 + c * 32 + h];
            a2 += xv * sW[5 * 512 + c * 32 + h];
        }
        sR[idx] = sCnt[row] * a1 + a2;
        sZ[idx] = zz;
    }
    __syncthreads();
    if (tid < 16) {
        float s = 0.0f;
#pragma unroll
        for (int t = 0; t < 16; t++) s += sAB1[t * 16 + tid];
        sAL1[tid] = s;
    }
    __syncthreads();
    {
        int r0 = tid >> 5, h = tid & 31;
        float ua = 0.0f, ub = 0.0f;
#pragma unroll
        for (int c = 0; c < 16; c++) {
            float w1b = sW[1 * 512 + c * 32 + h];
            float w3b = sW[3 * 512 + c * 32 + h];
            ua += sAB1[r0 * 16 + c] * w1b + sTB1[r0 * 16 + c] * w3b;
            ub += sAB1[(r0 + 8) * 16 + c] * w1b + sTB1[(r0 + 8) * 16 + c] * w3b;
        }
        sU1[r0 * 32 + h] = ua;
        sU1[(r0 + 8) * 32 + h] = ub;
    }
    if (tid < HD) {
        float s = 0.0f;
#pragma unroll
        for (int c = 0; c < 16; c++) s += sAL1[c] * sW[4 * 512 + c * 32 + tid];
        sD1[tid] = s;
    }
    __syncthreads();
    {   // y1 = U1 + b1 + delta*D1 + valid*R[i] + sum_t p_ij[t]*Z[t]
        ull y1[16];
#pragma unroll
        for (int k = 0; k < 16; k++) {
            ull u = *(const ull*)(sU1 + i * 32 + 2 * k);
            ull b = *(const ull*)(sB1 + 2 * k);
            y1[k] = addx2(u, b);
            if (i == j) y1[k] = addx2(y1[k], *(const ull*)(sD1 + 2 * k));
        }
        if (sM[i * 16 + j] >= 0) {
            const longlong2* rr = (const longlong2*)(sR + i * 32);
#pragma unroll
            for (int k8 = 0; k8 < 8; k8++) {
                longlong2 v = rr[k8];
                y1[2 * k8 + 0] = addx2(y1[2 * k8 + 0], (ull)v.x);
                y1[2 * k8 + 1] = addx2(y1[2 * k8 + 1], (ull)v.y);
            }
        }
#pragma unroll
        for (int t = 0; t < 16; t++) {
            unsigned vm = sVM[t];
            if (((vm >> i) & (vm >> j)) & 1) {
                const longlong2* zr = (const longlong2*)(sZ + t * 32);
#pragma unroll
                for (int k8 = 0; k8 < 8; k8++) {
                    longlong2 v = zr[k8];
                    y1[2 * k8 + 0] = addx2(y1[2 * k8 + 0], (ull)v.x);
                    y1[2 * k8 + 1] = addx2(y1[2 * k8 + 1], (ull)v.y);
                }
            }
        }
        // stage relu(y1) into tile1 at SWIZZLED offsets (row = tid)
        float* drow = tile1 + tid * 32;
#pragma unroll
        for (int q = 0; q < 8; q++) {
            float4 o;
            unpack2(y1[2 * q + 0], o.x, o.y);
            unpack2(y1[2 * q + 1], o.z, o.w);
            o.x = fmaxf(o.x, 0.0f); o.y = fmaxf(o.y, 0.0f);
            o.z = fmaxf(o.z, 0.0f); o.w = fmaxf(o.w, 0.0f);
            *(float4*)(drow + ((q ^ (tid & 7)) << 2)) = o;
        }
    }
    __syncthreads();
    {   // coalesced copy-out of the swizzled block
        float4* gdst = (float4*)(g_F1 + (size_t)n * 8192);
        const float4* sv = (const float4*)tile1;
#pragma unroll
        for (int k = 0; k < 8; k++) gdst[k * 256 + tid] = sv[k * 256 + tid];
    }
    __threadfence();
    __syncthreads();
    if (tid == 0) atomicExch(&g_flag[n], sMisc[0] + 1);   // publish

    // ============ Wc2 (C=32); slots 0 and 5 TRANSPOSED to [h-pair][c] ull rows ============
    for (int idx = tid; idx < 1024; idx += 256) {
        int c = idx >> 5, h = idx & 31;
        int tj = h >> 1, tl = h & 1;
        float s = W2[(0 * 32 + c) * 32 + h];
#pragma unroll
        for (int m = 6; m < 15; m++) s += W2[(m * 32 + c) * 32 + h];
        sW[0 * 1024 + tj * 64 + c * 2 + tl] = 16.0f * s + W2[(5 * 32 + c) * 32 + h];
        sW[1 * 1024 + c * 32 + h] = W2[(1 * 32 + c) * 32 + h];
        sW[2 * 1024 + c * 32 + h] = 16.0f * W2[(2 * 32 + c) * 32 + h];
        sW[3 * 1024 + c * 32 + h] = W2[(3 * 32 + c) * 32 + h];
        sW[4 * 1024 + c * 32 + h] = W2[(4 * 32 + c) * 32 + h];
        sW[5 * 1024 + tj * 64 + c * 2 + tl] = W2[(15 * 32 + c) * 32 + h];
    }
    if (tid < 16) {
        unsigned tgt = sMisc[0] + 1;
        const unsigned* fp = &g_flag[sNbr[tid]];
        unsigned v;
        do {
            asm volatile("ld.acquire.gpu.global.u32 %0, [%1];" : "=r"(v) : "l"(fp) : "memory");
        } while (v != tgt);
    }
    __syncthreads();

    // ============ layer 2 main loop (pair-collab on even iterations; bulk tile loads) ============
    if (tid == 0) {
        MBAR_EXPECT(mb0, 32768u);
        bulk_tile(t0a, g_F1 + (size_t)sNbr[0] * 8192, mb0);
    }

    ull st2[16];
#pragma unroll
    for (int c = 0; c < 16; c++) st2[c] = 0ull;
    ull y[16];
#pragma unroll
    for (int k = 0; k < 16; k++) y[k] = 0ull;
    ull stbA = 0ull, stbB = 0ull;
    int ph0 = 0, ph1 = 0;

    const longlong2* w0r = (const longlong2*)(sW + 0 * 1024 + j * 64);
    const longlong2* w5r = (const longlong2*)(sW + 5 * 1024 + j * 64);

    for (int tt = 0; tt < 8; tt++) {
        int t0 = 2 * tt, t1 = 2 * tt + 1;
        // ---- even iteration t0 (tile in tile0) ----
        {
            const float4* bufv = (const float4*)tile0;
            MBAR_WAIT(mb0, ph0); ph0 ^= 1;
            __syncthreads();
            if (tid == 0) {
                MBAR_EXPECT(mb1, 32768u);
                bulk_tile(t1a, g_F1 + (size_t)sNbr[t1] * 8192, mb1);
            }
            if (tt >= 1) {      // collab for tiles t0-1, t0-2 (slots disjoint from t0%3)
                int sA = ((t0 - 1) % 3) * 576, sB = ((t0 - 2) % 3) * 576;
                collab_pair(sGt + sA + i * 36, sDg + sA + i * 36,
                            sGt + sB + i * 36, sDg + sB + i * 36,
                            w0r, w5r,
                            &sYB[i * 17 + j], &sYB[272 + i * 17 + j]);
            }
            phaseA(t0, bufv, sGt, sDg, sQM, sM, aA, half, c4A, stbA, stbB);
            stGather(t0, bufv, sM, i, j, st2);
            if (tt >= 1 && tid < 32) {
                const float* gp = sGt + ((t0 - 1) % 3) * 576;
                float s = 0.0f;
#pragma unroll
                for (int a = 0; a < 16; a++) s += gp[a * 36 + tid];
                sSAB[(t0 - 1) * 32 + tid] = s;
            }
        }
        // ---- odd iteration t1 (tile in tile1) ----
        {
            const float4* bufv = (const float4*)tile1;
            MBAR_WAIT(mb1, ph1); ph1 ^= 1;
            __syncthreads();
            if (t1 < 15 && tid == 0) {
                MBAR_EXPECT(mb0, 32768u);
                bulk_tile(t0a, g_F1 + (size_t)sNbr[t1 + 1] * 8192, mb0);
            }
            if (tt >= 1) {      // pickup tiles collabed this tt: t0-1 (slot0), t0-2 (slot1)
                if (i == t0 - 1) {
#pragma unroll
                    for (int k = 0; k < 16; k++) y[k] = addx2(y[k], sYB[j * 17 + k]);
                }
                if (i == t0 - 2) {
#pragma unroll
                    for (int k = 0; k < 16; k++) y[k] = addx2(y[k], sYB[272 + j * 17 + k]);
                }
            }
            phaseA(t1, bufv, sGt, sDg, sQM, sM, aA, half, c4A, stbA, stbB);
            stGather(t1, bufv, sM, i, j, st2);
            if (tid < 32) {
                const float* gp = sGt + (t0 % 3) * 576;
                float s = 0.0f;
#pragma unroll
                for (int a = 0; a < 16; a++) s += gp[a * 36 + tid];
                sSAB[t0 * 32 + tid] = s;
            }
        }
    }

    // ============ epilogue ============
    __syncthreads();                           // E1: phase A(15/14) visible
    collab_pair(sGt + 0 * 576 + i * 36, sDg + 0 * 576 + i * 36,    // tile 15 (15%3=0)
                sGt + 2 * 576 + i * 36, sDg + 2 * 576 + i * 36,    // tile 14 (14%3=2)
                w0r, w5r,
                &sYB[i * 17 + j], &sYB[272 + i * 17 + j]);
    if (tid < 32) {                            // sum_ab(15)
        const float* gp = sGt + 0 * 576;
        float s = 0.0f;
#pragma unroll
        for (int a = 0; a < 16; a++) s += gp[a * 36 + tid];
        sSAB[15 * 32 + tid] = s;
    }
    if (half == 0) {                           // write sum_tb
        float4 o;
        unpack2(stbA, o.x, o.y);
        unpack2(stbB, o.z, o.w);
        *(float4*)(sSTB + aA * 32 + c4A * 4) = o;
    }
    __syncthreads();                           // E2
    if (i == 15) {
#pragma unroll
        for (int k = 0; k < 16; k++) y[k] = addx2(y[k], sYB[j * 17 + k]);
    }
    if (i == 14) {
#pragma unroll
        for (int k = 0; k < 16; k++) y[k] = addx2(y[k], sYB[272 + j * 17 + k]);
    }
    if (tid < 32) {
        float s = 0.0f;
#pragma unroll
        for (int t = 0; t < 16; t++) s += sSAB[t * 32 + tid];
        sSAL[tid] = s;
    }
    __syncthreads();                           // E3: sYB reads done; overlay now writable
    {   // U[row][h] into overlay
        int r0 = tid >> 5, h = tid & 31;
        float ua = 0.0f, ub = 0.0f;
#pragma unroll
        for (int c = 0; c < 32; c++) {
            float w1b = sW[1 * 1024 + c * 32 + h];
            float w3b = sW[3 * 1024 + c * 32 + h];
            ua += sSAB[r0 * 32 + c] * w1b + sSTB[r0 * 32 + c] * w3b;
            ub += sSAB[(r0 + 8) * 32 + c] * w1b + sSTB[(r0 + 8) * 32 + c] * w3b;
        }
        sU[r0 * 32 + h] = ua;
        sU[(r0 + 8) * 32 + h] = ub;
    }
    if (tid < 32) {
        float d = 0.0f;
#pragma unroll
        for (int c = 0; c < 32; c++) d += sSAL[c] * sW[4 * 1024 + c * 32 + tid];
        sD[tid] = d;
    }
    __syncthreads();                           // E4

    // ---- st GEMM (W2b, broadcast weights) ----
#pragma unroll
    for (int cc = 0; cc < 16; cc++) {
        float lo, hi;
        unpack2(st2[cc], lo, hi);
        gemm_row(y, pack2(lo), sW + 2 * 1024 + (2 * cc + 0) * 32);
        gemm_row(y, pack2(hi), sW + 2 * 1024 + (2 * cc + 1) * 32);
    }

    // ---- finalize: add U/D/bias(global), relu, dot fc(global), reduce ----
    float loc = 0.0f;
    const ull* b2p = (const ull*)b2;
    const ull* fwp = (const ull*)fcw;
#pragma unroll
    for (int k = 0; k < 16; k++) {
        ull u = *(const ull*)(sU + i * 32 + 2 * k);
        ull v = addx2(y[k], addx2(u, b2p[k]));
        if (i == j) v = addx2(v, *(const ull*)(sD + 2 * k));
        float lo, hi;
        unpack2(v, lo, hi);
        float w0, w1;
        unpack2(fwp[k], w0, w1);
        loc += fmaxf(lo, 0.0f) * w0 + fmaxf(hi, 0.0f) * w1;
    }
#pragma unroll
    for (int o = 16; o > 0; o >>= 1) loc += __shfl_xor_sync(0xffffffffu, loc, o);
    if ((tid & 31) == 0) sRED[tid >> 5] = loc;
    __syncthreads();
    if (tid == 0) {
        float s = 0.0f;
#pragma unroll
        for (int w = 0; w < 8; w++) s += sRED[w];
        atomicAdd(&g_acc, s);
        __threadfence();
        unsigned prev = atomicAdd(&g_done, 1);
        if (prev == NV - 1) {
            float tot = atomicAdd(&g_acc, 0.0f);
            out[0] = tot + fcb[0];
            g_acc = 0.0f;
            g_done = 0;
            g_epoch = sMisc[0] + 1;
            __threadfence();
        }
    }
}

extern "C" void kernel_launch(void* const* d_in, const int* in_sizes, int n_in,
                              void* d_out, int out_size) {
    const float* X   = (const float*)d_in[0];
    const int*   nbr = (const int*)d_in[1];
    const float* W1  = (const float*)d_in[2];
    const float* b1  = (const float*)d_in[3];
    const float* W2  = (const float*)d_in[4];
    const float* b2  = (const float*)d_in[5];
    const float* fcw = (const float*)d_in[6];
    const float* fcb = (const float*)d_in[7];
    float* out = (float*)d_out;

    cudaFuncSetAttribute(ccn_fused, cudaFuncAttributeMaxDynamicSharedMemorySize, SMEM_BYTES);
    ccn_fused<<<NV, 256, SMEM_BYTES>>>(nbr, X, W1, b1, W2, b2, fcw, fcb, out);
}

// round 16
// speedup vs baseline: 1.9429x; 1.9429x over previous
#include <cuda_runtime.h>

#define NV 256   // vertices
#define KD 16    // degree
#define HD 32    // hidden

// ---------------- globals ----------------
__device__ float g_F1[NV * 256 * HD];       // layer-1 output, 8 MB
__device__ unsigned g_flag[NV];             // per-vertex publish flag (epoch-stamped)
__device__ unsigned g_epoch;
__device__ unsigned g_done;
__device__ float g_acc;

typedef unsigned long long ull;

__device__ __forceinline__ ull pack2(float x) {
    ull r; asm("mov.b64 %0, {%1, %1};" : "=l"(r) : "f"(x)); return r;
}
__device__ __forceinline__ ull pack2f(float lo, float hi) {
    ull r; asm("mov.b64 %0, {%1, %2};" : "=l"(r) : "f"(lo), "f"(hi)); return r;
}
__device__ __forceinline__ void unpack2(ull v, float& lo, float& hi) {
    asm("mov.b64 {%0, %1}, %2;" : "=f"(lo), "=f"(hi) : "l"(v));
}
__device__ __forceinline__ void dfma(ull& acc, ull a, ull b) {
    asm("fma.rn.f32x2 %0, %1, %2, %0;" : "+l"(acc) : "l"(a), "l"(b));
}
__device__ __forceinline__ ull addx2(ull a, ull b) {
    ull r; asm("add.rn.f32x2 %0, %1, %2;" : "=l"(r) : "l"(a), "l"(b)); return r;
}
__device__ __forceinline__ void gemm_row(ull* y, ull a, const float* wrow) {
    const longlong2* w = (const longlong2*)wrow;
#pragma unroll
    for (int k8 = 0; k8 < 8; k8++) {
        longlong2 v = w[k8];
        dfma(y[2 * k8 + 0], a, (ull)v.x);
        dfma(y[2 * k8 + 1], a, (ull)v.y);
    }
}
__device__ __forceinline__ void cp16(float* sdst, const float4* gsrc) {
    unsigned s = (unsigned)__cvta_generic_to_shared(sdst);
    asm volatile("cp.async.cg.shared.global [%0], [%1], 16;" :: "r"(s), "l"(gsrc));
}

// ---------------- smem layout (floats) ----------------
// layer-2 sW layout: w0T [16][68] @0 | w5T [16][68] @1088 | W1b @2176 | W2b @3200 | W3b @4224 | W4b @5248
#define OFF_W     0          // 6272 : Wc1 (first 3072, row-major) then Wc2 (layout above)
#define OFF_T0    6272       // 8192 : tile0 (layer1 scratch aliases here)
#define OFF_T1    14464      // 8192 : tile1
#define OFF_GT    22656      // 1728 : sGt triple buffer [3][16][36]
#define OFF_DG    24384      // 1728 : sDiag triple buffer
#define OFF_SAB   26112      // 512
#define OFF_STB   26624      // 512
#define OFF_SAL   27136      // 32
#define OFF_YB    27168      // 1088 : ull[2][272]; OVERLAY: sU(512)+sD(32)+sRED(32) post-pickup
#define OFF_INT   28256      // nbr16,qm16,vm16,cnt16,misc4,M(64w) = 132 floats
#define SMEM_FLOATS (28256 + 132)
#define SMEM_BYTES  (SMEM_FLOATS * 4)

__device__ __forceinline__ void issue_tile(int t, float* buf, int tid, const int* sNbr) {
    const float4* src = (const float4*)(g_F1 + (size_t)sNbr[t] * 8192);
#pragma unroll
    for (int k = 0; k < 8; k++) {
        int g = k * 256 + tid;
        int r = g >> 3, c4 = g & 7;
        cp16(buf + r * 32 + ((c4 ^ (r & 7)) << 2), src + g);
    }
    asm volatile("cp.async.commit_group;");
}

// pair-tile collaborative gb/dg gemm with TRANSPOSED weights ([h-pair] rows of 68 floats)
__device__ __forceinline__ void collab_pair(const float* gA, const float* dA,
                                            const float* gB, const float* dB,
                                            const longlong2* w0r, const longlong2* w5r,
                                            ull* outA, ull* outB) {
    ull a0 = 0, a1 = 0, b0 = 0, b1 = 0;
#pragma unroll
    for (int c4 = 0; c4 < 8; c4++) {
        float4 ga = *(const float4*)(gA + c4 * 4);
        float4 da = *(const float4*)(dA + c4 * 4);
        float4 gb = *(const float4*)(gB + c4 * 4);
        float4 db = *(const float4*)(dB + c4 * 4);
        longlong2 w00 = w0r[2 * c4], w01 = w0r[2 * c4 + 1];
        longlong2 w50 = w5r[2 * c4], w51 = w5r[2 * c4 + 1];
        dfma(a0, pack2(ga.x), (ull)w00.x);
        dfma(b0, pack2(gb.x), (ull)w00.x);
        dfma(a1, pack2(da.x), (ull)w50.x);
        dfma(b1, pack2(db.x), (ull)w50.x);
        dfma(a0, pack2(ga.y), (ull)w00.y);
        dfma(b0, pack2(gb.y), (ull)w00.y);
        dfma(a1, pack2(da.y), (ull)w50.y);
        dfma(b1, pack2(db.y), (ull)w50.y);
        dfma(a0, pack2(ga.z), (ull)w01.x);
        dfma(b0, pack2(gb.z), (ull)w01.x);
        dfma(a1, pack2(da.z), (ull)w51.x);
        dfma(b1, pack2(db.z), (ull)w51.x);
        dfma(a0, pack2(ga.w), (ull)w01.y);
        dfma(b0, pack2(gb.w), (ull)w01.y);
        dfma(a1, pack2(da.w), (ull)w51.y);
        dfma(b1, pack2(db.w), (ull)w51.y);
    }
    *outA = addx2(a0, a1);
    *outB = addx2(b0, b1);
}

__device__ __forceinline__ void phaseA(int t, const float4* bufv, float* sGt, float* sDg,
                                       const unsigned* sQM, const signed char* sM,
                                       int aA, int half, int c4A, ull& stbA, ull& stbB) {
    int par = (t % 3) * 576;
    unsigned qm = sQM[t];
    int pA = sM[t * 16 + aA];
    ull acc0 = 0ull, acc1 = 0ull;
    if (pA >= 0) {
        int rbase = pA * 16 + half * 8;
#pragma unroll
        for (int k = 0; k < 8; k++) {
            if (qm & (1u << (half * 8 + k))) {
                int r = rbase + k;
                longlong2 v = *(const longlong2*)(bufv + r * 8 + (c4A ^ (r & 7)));
                acc0 = addx2(acc0, (ull)v.x);
                acc1 = addx2(acc1, (ull)v.y);
            }
        }
    }
    float f0, f1, f2, f3;
    unpack2(acc0, f0, f1);
    unpack2(acc1, f2, f3);
    f0 += __shfl_xor_sync(0xffffffffu, f0, 8);
    f1 += __shfl_xor_sync(0xffffffffu, f1, 8);
    f2 += __shfl_xor_sync(0xffffffffu, f2, 8);
    f3 += __shfl_xor_sync(0xffffffffu, f3, 8);
    stbA = addx2(stbA, pack2f(f0, f1));
    stbB = addx2(stbB, pack2f(f2, f3));
    if (half == 0) {
        float4 o; o.x = f0; o.y = f1; o.z = f2; o.w = f3;
        *(float4*)(sGt + par + aA * 36 + c4A * 4) = o;
    } else {
        longlong2 dv; dv.x = 0; dv.y = 0;
        if (pA >= 0) {
            int rd = pA * 17;
            dv = *(const longlong2*)(bufv + rd * 8 + (c4A ^ (rd & 7)));
        }
        *(longlong2*)(sDg + par + aA * 36 + c4A * 4) = dv;
    }
}

__device__ __forceinline__ void stGather(int t, const float4* bufv, const signed char* sM,
                                         int i, int j, ull* st2) {
    int pa = sM[t * 16 + i], pb = sM[t * 16 + j];
    if ((pa | pb) >= 0) {
        int r = pa * 16 + pb;
#pragma unroll
        for (int c4 = 0; c4 < 8; c4++) {
            longlong2 v = *(const longlong2*)(bufv + r * 8 + (c4 ^ (r & 7)));
            st2[2 * c4 + 0] = addx2(st2[2 * c4 + 0], (ull)v.x);
            st2[2 * c4 + 1] = addx2(st2[2 * c4 + 1], (ull)v.y);
        }
    }
}

__global__ __launch_bounds__(256, 2) void ccn_fused(const int* __restrict__ nbrs,
                                                    const float* __restrict__ X,
                                                    const float* __restrict__ W1,
                                                    const float* __restrict__ b1,
                                                    const float* __restrict__ W2,
                                                    const float* __restrict__ b2,
                                                    const float* __restrict__ fcw,
                                                    const float* __restrict__ fcb,
                                                    float* __restrict__ out) {
    extern __shared__ float smem[];
    float* sW    = smem + OFF_W;
    float* tile0 = smem + OFF_T0;
    float* tile1 = smem + OFF_T1;
    float* sGt   = smem + OFF_GT;    // [3][16][36]
    float* sDg   = smem + OFF_DG;    // [3][16][36]
    float* sSAB  = smem + OFF_SAB;   // [16][32]
    float* sSTB  = smem + OFF_STB;   // [16][32]
    float* sSAL  = smem + OFF_SAL;
    ull*   sYB   = (ull*)(smem + OFF_YB);     // [2][272]; overlaid by sU/sD/sRED later
    float* sU    = smem + OFF_YB;             // valid after pickup barrier
    float* sD    = sU + 512;
    float* sRED  = sU + 544;
    int*      sNbr = (int*)(smem + OFF_INT);
    unsigned* sQM  = (unsigned*)(sNbr + 16);
    unsigned* sVM  = (unsigned*)(sQM + 16);
    float*    sCnt = (float*)(sVM + 16);
    unsigned* sMisc = (unsigned*)(sCnt + 16);
    signed char* sM = (signed char*)(sMisc + 4);     // 256

    // layer-1 scratch aliases inside tile0
    float* sXn  = tile0;          // 256
    float* sAB1 = tile0 + 256;    // 256
    float* sTB1 = tile0 + 512;    // 256
    float* sAL1 = tile0 + 768;    // 16
    float* sU1  = tile0 + 784;    // 512
    float* sD1  = tile0 + 1296;   // 32
    float* sB1  = tile0 + 1328;   // 32
    float* sR   = tile0 + 1360;   // 512 : per-row xv-term table
    float* sZ   = tile0 + 1872;   // 512 : Z = Xn @ W2b

    int n = blockIdx.x, tid = threadIdx.x;
    int i = tid >> 4, j = tid & 15;
    int aA = i;                    // phase-A row
    int half = (tid >> 3) & 1;     // phase-A q-half
    int c4A = tid & 7;             // phase-A float4 column

    // ============ stage 0 ============
    {
        int jv = nbrs[n * 16 + i];
        int target = nbrs[n * 16 + j];
        int r = -1;
#pragma unroll
        for (int p = 0; p < 16; p++)
            if (nbrs[jv * 16 + p] == target) r = p;
        sM[tid] = (signed char)r;                 // sM[t*16+a], t=i, a=j
        sXn[tid] = X[jv * 16 + j];
    }
    if (tid < 16) sNbr[tid] = nbrs[n * 16 + tid];
    // Wc1 (C=16): slot0=16*(W0+W6..14)+W5, 1=W1, 2=16*W2, 3=W3, 4=W4, 5=W15 (row-major)
    for (int idx = tid; idx < 512; idx += 256) {
        int c = idx >> 5, h = idx & 31;
        float s = W1[(0 * 16 + c) * 32 + h];
#pragma unroll
        for (int m = 6; m < 15; m++) s += W1[(m * 16 + c) * 32 + h];
        sW[0 * 512 + c * 32 + h] = 16.0f * s + W1[(5 * 16 + c) * 32 + h];
        sW[1 * 512 + c * 32 + h] = W1[(1 * 16 + c) * 32 + h];
        sW[2 * 512 + c * 32 + h] = 16.0f * W1[(2 * 16 + c) * 32 + h];
        sW[3 * 512 + c * 32 + h] = W1[(3 * 16 + c) * 32 + h];
        sW[4 * 512 + c * 32 + h] = W1[(4 * 16 + c) * 32 + h];
        sW[5 * 512 + c * 32 + h] = W1[(15 * 16 + c) * 32 + h];
    }
    if (tid < HD) sB1[tid] = b1[tid];
    if (tid == 0) sMisc[0] = g_epoch;
    __syncthreads();
    if (tid < 16) {
        unsigned vm = 0, qm = 0;
#pragma unroll
        for (int a = 0; a < 16; a++) {
            int p = sM[tid * 16 + a];
            if (p >= 0) { vm |= 1u << a; qm |= 1u << p; }
        }
        sVM[tid] = vm;
        sQM[tid] = qm;
        sCnt[tid] = (float)__popc(vm);
    }
    __syncthreads();

    // ============ layer 1 (closed forms + row-shared tables) ============
    sAB1[tid] = sCnt[i] * sCnt[i] * sXn[tid];
    {
        float s = 0.0f;
#pragma unroll
        for (int t = 0; t < 16; t++)
            if ((sVM[t] >> i) & 1) s += sCnt[t] * sXn[t * 16 + j];
        sTB1[tid] = s;
    }
    // R[row][h] = cnt_row*(Xn_row @ Wsb)[h] + (Xn_row @ W15)[h];  Z[row][h] = (Xn_row @ W2b)[h]
#pragma unroll
    for (int rep = 0; rep < 2; rep++) {
        int idx = tid + rep * 256;
        int row = idx >> 5, h = idx & 31;
        float a1 = 0.0f, a2 = 0.0f, zz = 0.0f;
#pragma unroll
        for (int c = 0; c < 16; c++) {
            float xv = sXn[row * 16 + c];
            a1 += xv * sW[0 * 512 + c * 32 + h];
            zz += xv * sW[2 * 512 + c * 32 + h];
            a2 += xv * sW[5 * 512 + c * 32 + h];
        }
        sR[idx] = sCnt[row] * a1 + a2;
        sZ[idx] = zz;
    }
    __syncthreads();
    if (tid < 16) {
        float s = 0.0f;
#pragma unroll
        for (int t = 0; t < 16; t++) s += sAB1[t * 16 + tid];
        sAL1[tid] = s;
    }
    __syncthreads();
    {
        int r0 = tid >> 5, h = tid & 31;
        float ua = 0.0f, ub = 0.0f;
#pragma unroll
        for (int c = 0; c < 16; c++) {
            float w1b = sW[1 * 512 + c * 32 + h];
            float w3b = sW[3 * 512 + c * 32 + h];
            ua += sAB1[r0 * 16 + c] * w1b + sTB1[r0 * 16 + c] * w3b;
            ub += sAB1[(r0 + 8) * 16 + c] * w1b + sTB1[(r0 + 8) * 16 + c] * w3b;
        }
        sU1[r0 * 32 + h] = ua;
        sU1[(r0 + 8) * 32 + h] = ub;
    }
    if (tid < HD) {
        float s = 0.0f;
#pragma unroll
        for (int c = 0; c < 16; c++) s += sAL1[c] * sW[4 * 512 + c * 32 + tid];
        sD1[tid] = s;
    }
    __syncthreads();
    {   // y1 = U1 + b1 + delta*D1 + valid*R[i] + sum_t p_ij[t]*Z[t]
        ull y1[16];
#pragma unroll
        for (int k = 0; k < 16; k++) {
            ull u = *(const ull*)(sU1 + i * 32 + 2 * k);
            ull b = *(const ull*)(sB1 + 2 * k);
            y1[k] = addx2(u, b);
            if (i == j) y1[k] = addx2(y1[k], *(const ull*)(sD1 + 2 * k));
        }
        if (sM[i * 16 + j] >= 0) {
            const longlong2* rr = (const longlong2*)(sR + i * 32);
#pragma unroll
            for (int k8 = 0; k8 < 8; k8++) {
                longlong2 v = rr[k8];
                y1[2 * k8 + 0] = addx2(y1[2 * k8 + 0], (ull)v.x);
                y1[2 * k8 + 1] = addx2(y1[2 * k8 + 1], (ull)v.y);
            }
        }
#pragma unroll
        for (int t = 0; t < 16; t++) {
            unsigned vm = sVM[t];
            if (((vm >> i) & (vm >> j)) & 1) {
                const longlong2* zr = (const longlong2*)(sZ + t * 32);
#pragma unroll
                for (int k8 = 0; k8 < 8; k8++) {
                    longlong2 v = zr[k8];
                    y1[2 * k8 + 0] = addx2(y1[2 * k8 + 0], (ull)v.x);
                    y1[2 * k8 + 1] = addx2(y1[2 * k8 + 1], (ull)v.y);
                }
            }
        }
        float* dst = g_F1 + (size_t)(n * 256 + tid) * 32;
#pragma unroll
        for (int q = 0; q < 8; q++) {
            float4 o;
            unpack2(y1[2 * q + 0], o.x, o.y);
            unpack2(y1[2 * q + 1], o.z, o.w);
            o.x = fmaxf(o.x, 0.0f); o.y = fmaxf(o.y, 0.0f);
            o.z = fmaxf(o.z, 0.0f); o.w = fmaxf(o.w, 0.0f);
            ((float4*)dst)[q] = o;
        }
    }
    __threadfence();
    __syncthreads();
    if (tid == 0) atomicExch(&g_flag[n], sMisc[0] + 1);   // publish

    // ============ Wc2 (C=32); slots 0/5 transposed to [h-pair][c] rows of 68 floats ============
    for (int idx = tid; idx < 1024; idx += 256) {
        int c = idx >> 5, h = idx & 31;
        int tj = h >> 1, tl = h & 1;
        float s = W2[(0 * 32 + c) * 32 + h];
#pragma unroll
        for (int m = 6; m < 15; m++) s += W2[(m * 32 + c) * 32 + h];
        sW[tj * 68 + c * 2 + tl]        = 16.0f * s + W2[(5 * 32 + c) * 32 + h];  // w0T
        sW[1088 + tj * 68 + c * 2 + tl] = W2[(15 * 32 + c) * 32 + h];             // w5T
        sW[2176 + c * 32 + h] = W2[(1 * 32 + c) * 32 + h];                        // W1b
        sW[3200 + c * 32 + h] = 16.0f * W2[(2 * 32 + c) * 32 + h];                // W2b
        sW[4224 + c * 32 + h] = W2[(3 * 32 + c) * 32 + h];                        // W3b
        sW[5248 + c * 32 + h] = W2[(4 * 32 + c) * 32 + h];                        // W4b
    }
    if (tid < 16) {
        unsigned tgt = sMisc[0] + 1;
        const unsigned* fp = &g_flag[sNbr[tid]];
        unsigned v;
        do {
            asm volatile("ld.acquire.gpu.global.u32 %0, [%1];" : "=r"(v) : "l"(fp) : "memory");
        } while (v != tgt);
    }
    __syncthreads();

    // ============ layer 2 main loop (pair-collab on even iterations) ============
    issue_tile(0, tile0, tid, sNbr);

    ull st2[16];
#pragma unroll
    for (int c = 0; c < 16; c++) st2[c] = 0ull;
    ull y[16];
#pragma unroll
    for (int k = 0; k < 16; k++) y[k] = 0ull;
    ull stbA = 0ull, stbB = 0ull;

    const longlong2* w0r = (const longlong2*)(sW + j * 68);
    const longlong2* w5r = (const longlong2*)(sW + 1088 + j * 68);

    for (int tt = 0; tt < 8; tt++) {
        int t0 = 2 * tt, t1 = 2 * tt + 1;
        // ---- even iteration t0 (tile in tile0) ----
        {
            const float4* bufv = (const float4*)tile0;
            asm volatile("cp.async.wait_group 0;");
            __syncthreads();
            issue_tile(t1, tile1, tid, sNbr);
            if (tt >= 1) {      // collab for tiles t0-1, t0-2 (slots disjoint from t0%3)
                int sA = ((t0 - 1) % 3) * 576, sB = ((t0 - 2) % 3) * 576;
                collab_pair(sGt + sA + i * 36, sDg + sA + i * 36,
                            sGt + sB + i * 36, sDg + sB + i * 36,
                            w0r, w5r,
                            &sYB[i * 17 + j], &sYB[272 + i * 17 + j]);
            }
            phaseA(t0, bufv, sGt, sDg, sQM, sM, aA, half, c4A, stbA, stbB);
            stGather(t0, bufv, sM, i, j, st2);
            if (tt >= 1 && tid < 32) {
                const float* gp = sGt + ((t0 - 1) % 3) * 576;
                float s = 0.0f;
#pragma unroll
                for (int a = 0; a < 16; a++) s += gp[a * 36 + tid];
                sSAB[(t0 - 1) * 32 + tid] = s;
            }
        }
        // ---- odd iteration t1 (tile in tile1) ----
        {
            const float4* bufv = (const float4*)tile1;
            asm volatile("cp.async.wait_group 0;");
            __syncthreads();
            if (t1 < 15) issue_tile(t1 + 1, tile0, tid, sNbr);
            if (tt >= 1) {      // pickup tiles collabed this tt: t0-1 (slot0), t0-2 (slot1)
                if (i == t0 - 1) {
#pragma unroll
                    for (int k = 0; k < 16; k++) y[k] = addx2(y[k], sYB[j * 17 + k]);
                }
                if (i == t0 - 2) {
#pragma unroll
                    for (int k = 0; k < 16; k++) y[k] = addx2(y[k], sYB[272 + j * 17 + k]);
                }
            }
            phaseA(t1, bufv, sGt, sDg, sQM, sM, aA, half, c4A, stbA, stbB);
            stGather(t1, bufv, sM, i, j, st2);
            if (tid < 32) {
                const float* gp = sGt + (t0 % 3) * 576;
                float s = 0.0f;
#pragma unroll
                for (int a = 0; a < 16; a++) s += gp[a * 36 + tid];
                sSAB[t0 * 32 + tid] = s;
            }
        }
    }

    // ============ epilogue ============
    __syncthreads();                           // E1: phase A(15/14) visible
    collab_pair(sGt + 0 * 576 + i * 36, sDg + 0 * 576 + i * 36,    // tile 15 (15%3=0)
                sGt + 2 * 576 + i * 36, sDg + 2 * 576 + i * 36,    // tile 14 (14%3=2)
                w0r, w5r,
                &sYB[i * 17 + j], &sYB[272 + i * 17 + j]);
    if (tid < 32) {                            // sum_ab(15)
        const float* gp = sGt + 0 * 576;
        float s = 0.0f;
#pragma unroll
        for (int a = 0; a < 16; a++) s += gp[a * 36 + tid];
        sSAB[15 * 32 + tid] = s;
    }
    if (half == 0) {                           // write sum_tb
        float4 o;
        unpack2(stbA, o.x, o.y);
        unpack2(stbB, o.z, o.w);
        *(float4*)(sSTB + aA * 32 + c4A * 4) = o;
    }
    __syncthreads();                           // E2
    if (i == 15) {
#pragma unroll
        for (int k = 0; k < 16; k++) y[k] = addx2(y[k], sYB[j * 17 + k]);
    }
    if (i == 14) {
#pragma unroll
        for (int k = 0; k < 16; k++) y[k] = addx2(y[k], sYB[272 + j * 17 + k]);
    }
    if (tid < 32) {
        float s = 0.0f;
#pragma unroll
        for (int t = 0; t < 16; t++) s += sSAB[t * 32 + tid];
        sSAL[tid] = s;
    }
    __syncthreads();                           // E3: sYB reads done; overlay now writable
    {   // U[row][h] into overlay
        int r0 = tid >> 5, h = tid & 31;
        float ua = 0.0f, ub = 0.0f;
#pragma unroll
        for (int c = 0; c < 32; c++) {
            float w1b = sW[2176 + c * 32 + h];
            float w3b = sW[4224 + c * 32 + h];
            ua += sSAB[r0 * 32 + c] * w1b + sSTB[r0 * 32 + c] * w3b;
            ub += sSAB[(r0 + 8) * 32 + c] * w1b + sSTB[(r0 + 8) * 32 + c] * w3b;
        }
        sU[r0 * 32 + h] = ua;
        sU[(r0 + 8) * 32 + h] = ub;
    }
    if (tid < 32) {
        float d = 0.0f;
#pragma unroll
        for (int c = 0; c < 32; c++) d += sSAL[c] * sW[5248 + c * 32 + tid];
        sD[tid] = d;
    }
    __syncthreads();                           // E4

    // ---- st GEMM (W2b, broadcast weights) ----
#pragma unroll
    for (int cc = 0; cc < 16; cc++) {
        float lo, hi;
        unpack2(st2[cc], lo, hi);
        gemm_row(y, pack2(lo), sW + 3200 + (2 * cc + 0) * 32);
        gemm_row(y, pack2(hi), sW + 3200 + (2 * cc + 1) * 32);
    }

    // ---- finalize: add U/D/bias(global), relu, dot fc(global), reduce ----
    float loc = 0.0f;
    const ull* b2p = (const ull*)b2;
    const ull* fwp = (const ull*)fcw;
#pragma unroll
    for (int k = 0; k < 16; k++) {
        ull u = *(const ull*)(sU + i * 32 + 2 * k);
        ull v = addx2(y[k], addx2(u, b2p[k]));
        if (i == j) v = addx2(v, *(const ull*)(sD + 2 * k));
        float lo, hi;
        unpack2(v, lo, hi);
        float w0, w1;
        unpack2(fwp[k], w0, w1);
        loc += fmaxf(lo, 0.0f) * w0 + fmaxf(hi, 0.0f) * w1;
    }
#pragma unroll
    for (int o = 16; o > 0; o >>= 1) loc += __shfl_xor_sync(0xffffffffu, loc, o);
    if ((tid & 31) == 0) sRED[tid >> 5] = loc;
    __syncthreads();
    if (tid == 0) {
        float s = 0.0f;
#pragma unroll
        for (int w = 0; w < 8; w++) s += sRED[w];
        atomicAdd(&g_acc, s);
        __threadfence();
        unsigned prev = atomicAdd(&g_done, 1);
        if (prev == NV - 1) {
            float tot = atomicAdd(&g_acc, 0.0f);
            out[0] = tot + fcb[0];
            g_acc = 0.0f;
            g_done = 0;
            g_epoch = sMisc[0] + 1;
            __threadfence();
        }
    }
}

extern "C" void kernel_launch(void* const* d_in, const int* in_sizes, int n_in,
                              void* d_out, int out_size) {
    const float* X   = (const float*)d_in[0];
    const int*   nbr = (const int*)d_in[1];
    const float* W1  = (const float*)d_in[2];
    const float* b1  = (const float*)d_in[3];
    const float* W2  = (const float*)d_in[4];
    const float* b2  = (const float*)d_in[5];
    const float* fcw = (const float*)d_in[6];
    const float* fcb = (const float*)d_in[7];
    float* out = (float*)d_out;

    cudaFuncSetAttribute(ccn_fused, cudaFuncAttributeMaxDynamicSharedMemorySize, SMEM_BYTES);
    ccn_fused<<<NV, 256, SMEM_BYTES>>>(nbr, X, W1, b1, W2, b2, fcw, fcb, out);
}

// round 17
// speedup vs baseline: 2.0198x; 1.0396x over previous
#include <cuda_runtime.h>

#define NV 256   // vertices
#define KD 16    // degree
#define HD 32    // hidden

// ---------------- globals ----------------
__device__ float g_F1[NV * 256 * HD];       // layer-1 output, 8 MB
__device__ unsigned g_flag[NV];             // per-vertex publish flag (epoch-stamped)
__device__ unsigned g_epoch;
__device__ unsigned g_done;
__device__ float g_acc;

typedef unsigned long long ull;

__device__ __forceinline__ ull pack2(float x) {
    ull r; asm("mov.b64 %0, {%1, %1};" : "=l"(r) : "f"(x)); return r;
}
__device__ __forceinline__ ull pack2f(float lo, float hi) {
    ull r; asm("mov.b64 %0, {%1, %2};" : "=l"(r) : "f"(lo), "f"(hi)); return r;
}
__device__ __forceinline__ void unpack2(ull v, float& lo, float& hi) {
    asm("mov.b64 {%0, %1}, %2;" : "=f"(lo), "=f"(hi) : "l"(v));
}
__device__ __forceinline__ void dfma(ull& acc, ull a, ull b) {
    asm("fma.rn.f32x2 %0, %1, %2, %0;" : "+l"(acc) : "l"(a), "l"(b));
}
__device__ __forceinline__ ull addx2(ull a, ull b) {
    ull r; asm("add.rn.f32x2 %0, %1, %2;" : "=l"(r) : "l"(a), "l"(b)); return r;
}
__device__ __forceinline__ void gemm_row(ull* y, ull a, const float* wrow) {
    const longlong2* w = (const longlong2*)wrow;
#pragma unroll
    for (int k8 = 0; k8 < 8; k8++) {
        longlong2 v = w[k8];
        dfma(y[2 * k8 + 0], a, (ull)v.x);
        dfma(y[2 * k8 + 1], a, (ull)v.y);
    }
}
__device__ __forceinline__ void cp16(float* sdst, const float4* gsrc) {
    unsigned s = (unsigned)__cvta_generic_to_shared(sdst);
    asm volatile("cp.async.cg.shared.global [%0], [%1], 16;" :: "r"(s), "l"(gsrc));
}

// ---------------- smem layout (floats) ----------------
#define OFF_W     0          // 3072 : layer1 [6][512]; layer2 {Wsb|W15|W2b} each 1024
#define OFF_T0    3072       // 8192 : tile0 (layer1 scratch aliases here)
#define OFF_T1    11264      // 8192 : tile1
#define OFF_GT    19456      // 2304 : sGt quad buffer [4][16][36]
#define OFF_DG    21760      // 2304 : sDiag quad buffer
#define OFF_SAB   24064      // 512
#define OFF_STB   24576      // 512
#define OFF_SAL   25088      // 32
#define OFF_YB    25120      // 2176 : ull[2 pair-parities][2 tiles][272]; overlay sU/sD/sRED later
#define OFF_INT   27296      // nbr16,qm16,vm16,cnt16,misc4,M(64w) = 132 floats
#define SMEM_FLOATS (27296 + 132)
#define SMEM_BYTES  (SMEM_FLOATS * 4)

__device__ __forceinline__ void issue_tile(int t, float* buf, int tid, const int* sNbr) {
    const float4* src = (const float4*)(g_F1 + (size_t)sNbr[t] * 8192);
#pragma unroll
    for (int k = 0; k < 8; k++) {
        int g = k * 256 + tid;
        int r = g >> 3, c4 = g & 7;
        cp16(buf + r * 32 + ((c4 ^ (r & 7)) << 2), src + g);
    }
    asm volatile("cp.async.commit_group;");
}

// half collab for a tile pair: 16 channels (ch selects the c-half), shared weight fetches
__device__ __forceinline__ void half_collab_pair(const float* gA, const float* dA,
                                                 const float* gB, const float* dB,
                                                 const float* w0b, const float* w5b,
                                                 int ch, ull* outA, ull* outB) {
    ull a0 = 0, a1 = 0, b0 = 0, b1 = 0;
    int co = ch * 16;
#pragma unroll
    for (int c4 = 0; c4 < 4; c4++) {
        float4 ga = *(const float4*)(gA + co + c4 * 4);
        float4 da = *(const float4*)(dA + co + c4 * 4);
        float4 gb = *(const float4*)(gB + co + c4 * 4);
        float4 db = *(const float4*)(dB + co + c4 * 4);
        float gav[4] = {ga.x, ga.y, ga.z, ga.w};
        float dav[4] = {da.x, da.y, da.z, da.w};
        float gbv[4] = {gb.x, gb.y, gb.z, gb.w};
        float dbv[4] = {db.x, db.y, db.z, db.w};
#pragma unroll
        for (int cl = 0; cl < 4; cl++) {
            int c = co + c4 * 4 + cl;
            ull w0 = *(const ull*)(w0b + c * 32);
            ull w5 = *(const ull*)(w5b + c * 32);
            dfma(a0, pack2(gav[cl]), w0);
            dfma(b0, pack2(gbv[cl]), w0);
            dfma(a1, pack2(dav[cl]), w5);
            dfma(b1, pack2(dbv[cl]), w5);
        }
    }
    *outA = addx2(a0, a1);
    *outB = addx2(b0, b1);
}

__device__ __forceinline__ void phaseA(int t, const float4* bufv, float* sGt, float* sDg,
                                       const unsigned* sQM, const signed char* sM,
                                       int aA, int half, int c4A, ull& stbA, ull& stbB) {
    int par = (t & 3) * 576;
    unsigned qm = sQM[t];
    int pA = sM[t * 16 + aA];
    ull acc0 = 0ull, acc1 = 0ull;
    if (pA >= 0) {
        int rbase = pA * 16 + half * 8;
#pragma unroll
        for (int k = 0; k < 8; k++) {
            if (qm & (1u << (half * 8 + k))) {
                int r = rbase + k;
                longlong2 v = *(const longlong2*)(bufv + r * 8 + (c4A ^ (r & 7)));
                acc0 = addx2(acc0, (ull)v.x);
                acc1 = addx2(acc1, (ull)v.y);
            }
        }
    }
    float f0, f1, f2, f3;
    unpack2(acc0, f0, f1);
    unpack2(acc1, f2, f3);
    f0 += __shfl_xor_sync(0xffffffffu, f0, 8);
    f1 += __shfl_xor_sync(0xffffffffu, f1, 8);
    f2 += __shfl_xor_sync(0xffffffffu, f2, 8);
    f3 += __shfl_xor_sync(0xffffffffu, f3, 8);
    stbA = addx2(stbA, pack2f(f0, f1));
    stbB = addx2(stbB, pack2f(f2, f3));
    if (half == 0) {
        float4 o; o.x = f0; o.y = f1; o.z = f2; o.w = f3;
        *(float4*)(sGt + par + aA * 36 + c4A * 4) = o;
    } else {
        longlong2 dv; dv.x = 0; dv.y = 0;
        if (pA >= 0) {
            int rd = pA * 17;
            dv = *(const longlong2*)(bufv + rd * 8 + (c4A ^ (rd & 7)));
        }
        *(longlong2*)(sDg + par + aA * 36 + c4A * 4) = dv;
    }
}

__device__ __forceinline__ void stGather(int t, const float4* bufv, const signed char* sM,
                                         int i, int j, ull* st2) {
    int pa = sM[t * 16 + i], pb = sM[t * 16 + j];
    if ((pa | pb) >= 0) {
        int r = pa * 16 + pb;
#pragma unroll
        for (int c4 = 0; c4 < 8; c4++) {
            longlong2 v = *(const longlong2*)(bufv + r * 8 + (c4 ^ (r & 7)));
            st2[2 * c4 + 0] = addx2(st2[2 * c4 + 0], (ull)v.x);
            st2[2 * c4 + 1] = addx2(st2[2 * c4 + 1], (ull)v.y);
        }
    }
}

__global__ __launch_bounds__(256, 2) void ccn_fused(const int* __restrict__ nbrs,
                                                    const float* __restrict__ X,
                                                    const float* __restrict__ W1,
                                                    const float* __restrict__ b1,
                                                    const float* __restrict__ W2,
                                                    const float* __restrict__ b2,
                                                    const float* __restrict__ fcw,
                                                    const float* __restrict__ fcb,
                                                    float* __restrict__ out) {
    extern __shared__ float smem[];
    float* sW    = smem + OFF_W;
    float* tile0 = smem + OFF_T0;
    float* tile1 = smem + OFF_T1;
    float* sGt   = smem + OFF_GT;    // [4][16][36]
    float* sDg   = smem + OFF_DG;    // [4][16][36]
    float* sSAB  = smem + OFF_SAB;   // [16][32]
    float* sSTB  = smem + OFF_STB;   // [16][32]
    float* sSAL  = smem + OFF_SAL;
    ull*   sYB   = (ull*)(smem + OFF_YB);     // [2][544]; overlaid by sU/sD/sRED later
    float* sU    = smem + OFF_YB;             // valid after final pickup barrier
    float* sD    = sU + 512;
    float* sRED  = sU + 544;
    int*      sNbr = (int*)(smem + OFF_INT);
    unsigned* sQM  = (unsigned*)(sNbr + 16);
    unsigned* sVM  = (unsigned*)(sQM + 16);
    float*    sCnt = (float*)(sVM + 16);
    unsigned* sMisc = (unsigned*)(sCnt + 16);
    signed char* sM = (signed char*)(sMisc + 4);     // 256

    // layer-1 scratch aliases inside tile0
    float* sXn  = tile0;          // 256
    float* sAB1 = tile0 + 256;    // 256
    float* sTB1 = tile0 + 512;    // 256
    float* sAL1 = tile0 + 768;    // 16
    float* sU1  = tile0 + 784;    // 512
    float* sD1  = tile0 + 1296;   // 32
    float* sB1  = tile0 + 1328;   // 32
    float* sR   = tile0 + 1360;   // 512 : per-row xv-term table
    float* sZ   = tile0 + 1872;   // 512 : Z = Xn @ W2b

    int n = blockIdx.x, tid = threadIdx.x;
    int i = tid >> 4, j = tid & 15;
    int aA = i;                    // phase-A row
    int half = (tid >> 3) & 1;     // phase-A q-half
    int c4A = tid & 7;             // phase-A float4 column

    // ============ stage 0 ============
    {
        int jv = nbrs[n * 16 + i];
        int target = nbrs[n * 16 + j];
        int r = -1;
#pragma unroll
        for (int p = 0; p < 16; p++)
            if (nbrs[jv * 16 + p] == target) r = p;
        sM[tid] = (signed char)r;                 // sM[t*16+a], t=i, a=j
        sXn[tid] = X[jv * 16 + j];
    }
    if (tid < 16) sNbr[tid] = nbrs[n * 16 + tid];
    // Wc1 (C=16): slot0=16*(W0+W6..14)+W5, 1=W1, 2=16*W2, 3=W3, 4=W4, 5=W15 (row-major)
    for (int idx = tid; idx < 512; idx += 256) {
        int c = idx >> 5, h = idx & 31;
        float s = W1[(0 * 16 + c) * 32 + h];
#pragma unroll
        for (int m = 6; m < 15; m++) s += W1[(m * 16 + c) * 32 + h];
        sW[0 * 512 + c * 32 + h] = 16.0f * s + W1[(5 * 16 + c) * 32 + h];
        sW[1 * 512 + c * 32 + h] = W1[(1 * 16 + c) * 32 + h];
        sW[2 * 512 + c * 32 + h] = 16.0f * W1[(2 * 16 + c) * 32 + h];
        sW[3 * 512 + c * 32 + h] = W1[(3 * 16 + c) * 32 + h];
        sW[4 * 512 + c * 32 + h] = W1[(4 * 16 + c) * 32 + h];
        sW[5 * 512 + c * 32 + h] = W1[(15 * 16 + c) * 32 + h];
    }
    if (tid < HD) sB1[tid] = b1[tid];
    if (tid == 0) sMisc[0] = g_epoch;
    __syncthreads();
    if (tid < 16) {
        unsigned vm = 0, qm = 0;
#pragma unroll
        for (int a = 0; a < 16; a++) {
            int p = sM[tid * 16 + a];
            if (p >= 0) { vm |= 1u << a; qm |= 1u << p; }
        }
        sVM[tid] = vm;
        sQM[tid] = qm;
        sCnt[tid] = (float)__popc(vm);
    }
    __syncthreads();

    // ============ layer 1 (closed forms + row-shared tables) ============
    sAB1[tid] = sCnt[i] * sCnt[i] * sXn[tid];
    {
        float s = 0.0f;
#pragma unroll
        for (int t = 0; t < 16; t++)
            if ((sVM[t] >> i) & 1) s += sCnt[t] * sXn[t * 16 + j];
        sTB1[tid] = s;
    }
#pragma unroll
    for (int rep = 0; rep < 2; rep++) {
        int idx = tid + rep * 256;
        int row = idx >> 5, h = idx & 31;
        float a1 = 0.0f, a2 = 0.0f, zz = 0.0f;
#pragma unroll
        for (int c = 0; c < 16; c++) {
            float xv = sXn[row * 16 + c];
            a1 += xv * sW[0 * 512 + c * 32 + h];
            zz += xv * sW[2 * 512 + c * 32 + h];
            a2 += xv * sW[5 * 512 + c * 32 + h];
        }
        sR[idx] = sCnt[row] * a1 + a2;
        sZ[idx] = zz;
    }
    __syncthreads();
    if (tid < 16) {
        float s = 0.0f;
#pragma unroll
        for (int t = 0; t < 16; t++) s += sAB1[t * 16 + tid];
        sAL1[tid] = s;
    }
    __syncthreads();
    {
        int r0 = tid >> 5, h = tid & 31;
        float ua = 0.0f, ub = 0.0f;
#pragma unroll
        for (int c = 0; c < 16; c++) {
            float w1b = sW[1 * 512 + c * 32 + h];
            float w3b = sW[3 * 512 + c * 32 + h];
            ua += sAB1[r0 * 16 + c] * w1b + sTB1[r0 * 16 + c] * w3b;
            ub += sAB1[(r0 + 8) * 16 + c] * w1b + sTB1[(r0 + 8) * 16 + c] * w3b;
        }
        sU1[r0 * 32 + h] = ua;
        sU1[(r0 + 8) * 32 + h] = ub;
    }
    if (tid < HD) {
        float s = 0.0f;
#pragma unroll
        for (int c = 0; c < 16; c++) s += sAL1[c] * sW[4 * 512 + c * 32 + tid];
        sD1[tid] = s;
    }
    __syncthreads();
    {   // y1 = U1 + b1 + delta*D1 + valid*R[i] + sum_t p_ij[t]*Z[t]
        ull y1[16];
#pragma unroll
        for (int k = 0; k < 16; k++) {
            ull u = *(const ull*)(sU1 + i * 32 + 2 * k);
            ull b = *(const ull*)(sB1 + 2 * k);
            y1[k] = addx2(u, b);
            if (i == j) y1[k] = addx2(y1[k], *(const ull*)(sD1 + 2 * k));
        }
        if (sM[i * 16 + j] >= 0) {
            const longlong2* rr = (const longlong2*)(sR + i * 32);
#pragma unroll
            for (int k8 = 0; k8 < 8; k8++) {
                longlong2 v = rr[k8];
                y1[2 * k8 + 0] = addx2(y1[2 * k8 + 0], (ull)v.x);
                y1[2 * k8 + 1] = addx2(y1[2 * k8 + 1], (ull)v.y);
            }
        }
#pragma unroll
        for (int t = 0; t < 16; t++) {
            unsigned vm = sVM[t];
            if (((vm >> i) & (vm >> j)) & 1) {
                const longlong2* zr = (const longlong2*)(sZ + t * 32);
#pragma unroll
                for (int k8 = 0; k8 < 8; k8++) {
                    longlong2 v = zr[k8];
                    y1[2 * k8 + 0] = addx2(y1[2 * k8 + 0], (ull)v.x);
                    y1[2 * k8 + 1] = addx2(y1[2 * k8 + 1], (ull)v.y);
                }
            }
        }
        float* dst = g_F1 + (size_t)(n * 256 + tid) * 32;
#pragma unroll
        for (int q = 0; q < 8; q++) {
            float4 o;
            unpack2(y1[2 * q + 0], o.x, o.y);
            unpack2(y1[2 * q + 1], o.z, o.w);
            o.x = fmaxf(o.x, 0.0f); o.y = fmaxf(o.y, 0.0f);
            o.z = fmaxf(o.z, 0.0f); o.w = fmaxf(o.w, 0.0f);
            ((float4*)dst)[q] = o;
        }
    }
    __threadfence();
    __syncthreads();
    if (tid == 0) atomicExch(&g_flag[n], sMisc[0] + 1);   // publish

    // ============ layer-2 weights: Wsb | W15 | W2b (overwrites layer-1 sW) ============
    for (int idx = tid; idx < 1024; idx += 256) {
        int c = idx >> 5, h = idx & 31;
        float s = W2[(0 * 32 + c) * 32 + h];
#pragma unroll
        for (int m = 6; m < 15; m++) s += W2[(m * 32 + c) * 32 + h];
        sW[c * 32 + h]        = 16.0f * s + W2[(5 * 32 + c) * 32 + h];   // Wsb
        sW[1024 + c * 32 + h] = W2[(15 * 32 + c) * 32 + h];              // W15
        sW[2048 + c * 32 + h] = 16.0f * W2[(2 * 32 + c) * 32 + h];       // W2b
    }
    if (tid < 16) {
        unsigned tgt = sMisc[0] + 1;
        const unsigned* fp = &g_flag[sNbr[tid]];
        unsigned v;
        do {
            asm volatile("ld.acquire.gpu.global.u32 %0, [%1];" : "=r"(v) : "l"(fp) : "memory");
        } while (v != tgt);
    }
    __syncthreads();

    // ============ layer 2 main loop (balanced half-collabs every iteration) ============
    issue_tile(0, tile0, tid, sNbr);

    ull st2[16];
#pragma unroll
    for (int c = 0; c < 16; c++) st2[c] = 0ull;
    ull y[16];
#pragma unroll
    for (int k = 0; k < 16; k++) y[k] = 0ull;
    ull stbA = 0ull, stbB = 0ull;

    const float* w0b = sW + 2 * j;
    const float* w5b = sW + 1024 + 2 * j;

    for (int t = 0; t < 16; t++) {
        float* buf = (t & 1) ? tile1 : tile0;
        const float4* bufv = (const float4*)buf;
        asm volatile("cp.async.wait_group 0;");
        __syncthreads();
        if (t < 15) issue_tile(t + 1, (t & 1) ? tile0 : tile1, tid, sNbr);

        int pb = (t >> 1) & 1;
        ull* ybuf = sYB + pb * 544;
        if ((t & 1) == 0) {
            if (t >= 4) {   // pickup pair (t-3, t-4) from the other parity buffer
                ull* pk = sYB + (pb ^ 1) * 544;
                if (i == t - 3) {
#pragma unroll
                    for (int k = 0; k < 16; k++) y[k] = addx2(y[k], pk[j * 17 + k]);
                }
                if (i == t - 4) {
#pragma unroll
                    for (int k = 0; k < 16; k++) y[k] = addx2(y[k], pk[272 + j * 17 + k]);
                }
            }
            if (t >= 2) {   // half0 collab for pair (t-1, t-2)
                int sA = ((t - 1) & 3) * 576, sB = ((t - 2) & 3) * 576;
                ull oA, oB;
                half_collab_pair(sGt + sA + i * 36, sDg + sA + i * 36,
                                 sGt + sB + i * 36, sDg + sB + i * 36,
                                 w0b, w5b, 0, &oA, &oB);
                ybuf[i * 17 + j] = oA;
                ybuf[272 + i * 17 + j] = oB;
            }
        } else {
            if (t >= 3) {   // half1 collab for pair (t-2, t-3), accumulate
                int sA = ((t - 2) & 3) * 576, sB = ((t - 3) & 3) * 576;
                ull oA, oB;
                half_collab_pair(sGt + sA + i * 36, sDg + sA + i * 36,
                                 sGt + sB + i * 36, sDg + sB + i * 36,
                                 w0b, w5b, 1, &oA, &oB);
                ybuf[i * 17 + j] = addx2(ybuf[i * 17 + j], oA);
                ybuf[272 + i * 17 + j] = addx2(ybuf[272 + i * 17 + j], oB);
            }
        }
        phaseA(t, bufv, sGt, sDg, sQM, sM, aA, half, c4A, stbA, stbB);
        stGather(t, bufv, sM, i, j, st2);
        if (t >= 1 && tid < 32) {
            const float* gp = sGt + ((t - 1) & 3) * 576;
            float s = 0.0f;
#pragma unroll
            for (int a = 0; a < 16; a++) s += gp[a * 36 + tid];
            sSAB[(t - 1) * 32 + tid] = s;
        }
    }

    // ============ epilogue ============
    __syncthreads();                           // E1: phaseA(15) done; sYB pair(13,12) complete in buf 1
    {   // pickup pair (13,12) from buffer 1
        ull* pk = sYB + 544;
        if (i == 13) {
#pragma unroll
            for (int k = 0; k < 16; k++) y[k] = addx2(y[k], pk[j * 17 + k]);
        }
        if (i == 12) {
#pragma unroll
            for (int k = 0; k < 16; k++) y[k] = addx2(y[k], pk[272 + j * 17 + k]);
        }
    }
    {   // full collab pair (15,14) into buffer 0 (slots 15&3=3, 14&3=2)
        ull oA0, oB0, oA1, oB1;
        half_collab_pair(sGt + 3 * 576 + i * 36, sDg + 3 * 576 + i * 36,
                         sGt + 2 * 576 + i * 36, sDg + 2 * 576 + i * 36,
                         w0b, w5b, 0, &oA0, &oB0);
        half_collab_pair(sGt + 3 * 576 + i * 36, sDg + 3 * 576 + i * 36,
                         sGt + 2 * 576 + i * 36, sDg + 2 * 576 + i * 36,
                         w0b, w5b, 1, &oA1, &oB1);
        sYB[i * 17 + j] = addx2(oA0, oA1);
        sYB[272 + i * 17 + j] = addx2(oB0, oB1);
    }
    if (tid < 32) {                            // sum_ab(15), slot 3
        const float* gp = sGt + 3 * 576;
        float s = 0.0f;
#pragma unroll
        for (int a = 0; a < 16; a++) s += gp[a * 36 + tid];
        sSAB[15 * 32 + tid] = s;
    }
    if (half == 0) {                           // write sum_tb
        float4 o;
        unpack2(stbA, o.x, o.y);
        unpack2(stbB, o.z, o.w);
        *(float4*)(sSTB + aA * 32 + c4A * 4) = o;
    }
    __syncthreads();                           // E2
    {   // pickup pair (15,14) from buffer 0
        if (i == 15) {
#pragma unroll
            for (int k = 0; k < 16; k++) y[k] = addx2(y[k], sYB[j * 17 + k]);
        }
        if (i == 14) {
#pragma unroll
            for (int k = 0; k < 16; k++) y[k] = addx2(y[k], sYB[272 + j * 17 + k]);
        }
    }
    if (tid < 32) {
        float s = 0.0f;
#pragma unroll
        for (int t = 0; t < 16; t++) s += sSAB[t * 32 + tid];
        sSAL[tid] = s;
    }
    __syncthreads();                           // E3: sYB reads done; overlay writable
    {   // U[row][h] into overlay; W1b/W3b straight from global (L2-resident, coalesced)
        int r0 = tid >> 5, h = tid & 31;
        float ua = 0.0f, ub = 0.0f;
#pragma unroll
        for (int c = 0; c < 32; c++) {
            float w1b = __ldg(&W2[(1 * 32 + c) * 32 + h]);
            float w3b = __ldg(&W2[(3 * 32 + c) * 32 + h]);
            ua += sSAB[r0 * 32 + c] * w1b + sSTB[r0 * 32 + c] * w3b;
            ub += sSAB[(r0 + 8) * 32 + c] * w1b + sSTB[(r0 + 8) * 32 + c] * w3b;
        }
        sU[r0 * 32 + h] = ua;
        sU[(r0 + 8) * 32 + h] = ub;
    }
    if (tid < 32) {
        float d = 0.0f;
#pragma unroll
        for (int c = 0; c < 32; c++) d += sSAL[c] * __ldg(&W2[(4 * 32 + c) * 32 + tid]);
        sD[tid] = d;
    }
    __syncthreads();                           // E4

    // ---- st GEMM (W2b, broadcast weights) ----
#pragma unroll
    for (int cc = 0; cc < 16; cc++) {
        float lo, hi;
        unpack2(st2[cc], lo, hi);
        gemm_row(y, pack2(lo), sW + 2048 + (2 * cc + 0) * 32);
        gemm_row(y, pack2(hi), sW + 2048 + (2 * cc + 1) * 32);
    }

    // ---- finalize: add U/D/bias(global), relu, dot fc(global), reduce ----
    float loc = 0.0f;
    const ull* b2p = (const ull*)b2;
    const ull* fwp = (const ull*)fcw;
#pragma unroll
    for (int k = 0; k < 16; k++) {
        ull u = *(const ull*)(sU + i * 32 + 2 * k);
        ull v = addx2(y[k], addx2(u, b2p[k]));
        if (i == j) v = addx2(v, *(const ull*)(sD + 2 * k));
        float lo, hi;
        unpack2(v, lo, hi);
        float w0, w1;
        unpack2(fwp[k], w0, w1);
        loc += fmaxf(lo, 0.0f) * w0 + fmaxf(hi, 0.0f) * w1;
    }
#pragma unroll
    for (int o = 16; o > 0; o >>= 1) loc += __shfl_xor_sync(0xffffffffu, loc, o);
    if ((tid & 31) == 0) sRED[tid >> 5] = loc;
    __syncthreads();
    if (tid == 0) {
        float s = 0.0f;
#pragma unroll
        for (int w = 0; w < 8; w++) s += sRED[w];
        atomicAdd(&g_acc, s);
        __threadfence();
        unsigned prev = atomicAdd(&g_done, 1);
        if (prev == NV - 1) {
            float tot = atomicAdd(&g_acc, 0.0f);
            out[0] = tot + fcb[0];
            g_acc = 0.0f;
            g_done = 0;
            g_epoch = sMisc[0] + 1;
            __threadfence();
        }
    }
}

extern "C" void kernel_launch(void* const* d_in, const int* in_sizes, int n_in,
                              void* d_out, int out_size) {
    const float* X   = (const float*)d_in[0];
    const int*   nbr = (const int*)d_in[1];
    const float* W1  = (const float*)d_in[2];
    const float* b1  = (const float*)d_in[3];
    const float* W2  = (const float*)d_in[4];
    const float* b2  = (const float*)d_in[5];
    const float* fcw = (const float*)d_in[6];
    const float* fcb = (const float*)d_in[7];
    float* out = (float*)d_out;

    cudaFuncSetAttribute(ccn_fused, cudaFuncAttributeMaxDynamicSharedMemorySize, SMEM_BYTES);
    ccn_fused<<<NV, 256, SMEM_BYTES>>>(nbr, X, W1, b1, W2, b2, fcw, fcb, out);
}